// round 3
// baseline (speedup 1.0000x reference)
#include <cuda_runtime.h>
#include <math.h>

#define N_NODES 8192
#define N_EDGES 262144
#define IN_DIM  64
#define H_DIM   128
#define L_LAYERS 4
#define NGRAPH  32
#define OUT_DIM 10

// ---------------- scratch (static device globals; no allocation) ----------------
__device__ float d_h [N_NODES*H_DIM];
__device__ float d_hn[N_NODES*H_DIM];
__device__ float d_q [N_NODES*H_DIM];
__device__ float d_k [N_NODES*H_DIM];
__device__ float d_v [N_NODES*H_DIM];
__device__ float d_t1[N_NODES*2*H_DIM];
__device__ int   d_counts[N_NODES];
__device__ int   d_offs[N_NODES+1];
__device__ int   d_cursor[N_NODES];
__device__ int   d_packed[N_EDGES];      // src | (p<<13) | (d<<17)
__device__ float d_pooled[NGRAPH*H_DIM];

// ---------------- preprocess ----------------
__global__ void zero_pre_kernel() {
    int i = blockIdx.x*blockDim.x + threadIdx.x;
    if (i < N_NODES) d_counts[i] = 0;
    if (i < NGRAPH*H_DIM) d_pooled[i] = 0.0f;
}

__global__ void hist_kernel(const int* __restrict__ dst) {
    int e = blockIdx.x*blockDim.x + threadIdx.x;
    if (e < N_EDGES) atomicAdd(&d_counts[dst[e]], 1);
}

// single-block exclusive scan over 8192 counts (1024 threads x 8)
__global__ void scan_kernel() {
    __shared__ int s[1024];
    int tid = threadIdx.x;
    int local[8]; int sum = 0;
#pragma unroll
    for (int j = 0; j < 8; j++) { local[j] = sum; sum += d_counts[tid*8 + j]; }
    s[tid] = sum;
    __syncthreads();
    for (int off = 1; off < 1024; off <<= 1) {
        int v = 0;
        if (tid >= off) v = s[tid - off];
        __syncthreads();
        s[tid] += v;
        __syncthreads();
    }
    int base = tid ? s[tid-1] : 0;
#pragma unroll
    for (int j = 0; j < 8; j++) {
        int val = base + local[j];
        d_offs[tid*8 + j]   = val;
        d_cursor[tid*8 + j] = val;
    }
    if (tid == 1023) d_offs[N_NODES] = s[1023];
}

__global__ void scatter_kernel(const int* __restrict__ src, const int* __restrict__ dst,
                               const int* __restrict__ pmat, const int* __restrict__ dmat) {
    int e = blockIdx.x*blockDim.x + threadIdx.x;
    if (e >= N_EDGES) return;
    int s = src[e], d = dst[e];
    int pos = atomicAdd(&d_cursor[d], 1);
    long idx = (long)s * N_NODES + d;
    int p  = pmat[idx];
    int dd = dmat[idx];
    d_packed[pos] = s | (p << 13) | (dd << 17);
}

// ---------------- layernorm: d_hn = LN(d_h) * s + b ----------------
__global__ void ln_kernel(const float* __restrict__ sc, const float* __restrict__ bi) {
    int row  = blockIdx.x * 8 + (threadIdx.x >> 5);
    int lane = threadIdx.x & 31;
    float4 x = ((const float4*)(d_h + row*H_DIM))[lane];
    float sum = x.x + x.y + x.z + x.w;
#pragma unroll
    for (int o = 16; o; o >>= 1) sum += __shfl_xor_sync(0xffffffffu, sum, o);
    float mean = sum * (1.0f/128.0f);
    float dx0 = x.x - mean, dx1 = x.y - mean, dx2 = x.z - mean, dx3 = x.w - mean;
    float sq = dx0*dx0 + dx1*dx1 + dx2*dx2 + dx3*dx3;
#pragma unroll
    for (int o = 16; o; o >>= 1) sq += __shfl_xor_sync(0xffffffffu, sq, o);
    float inv = rsqrtf(sq * (1.0f/128.0f) + 1e-5f);
    float4 s4 = ((const float4*)sc)[lane];
    float4 b4 = ((const float4*)bi)[lane];
    float4 o;
    o.x = dx0*inv*s4.x + b4.x;
    o.y = dx1*inv*s4.y + b4.y;
    o.z = dx2*inv*s4.z + b4.z;
    o.w = dx3*inv*s4.w + b4.w;
    ((float4*)(d_hn + row*H_DIM))[lane] = o;
}

// ---------------- generic SGEMM: C = act(A[M,K] @ B[K,Nc] + bias) ----------------
// mode: 0=store, 1=gelu(exact erf), 2=relu, 3=add to C (residual)
__global__ void sgemm_kernel(const float* __restrict__ A, const float* __restrict__ B,
                             const float* __restrict__ bias, float* __restrict__ C,
                             int M, int K, int Nc, int mode) {
    __shared__ float As[16*68];
    __shared__ float Bs[16*68];
    int tid = threadIdx.x;
    int tx = tid & 15, ty = tid >> 4;
    int row0 = blockIdx.x * 64;
    int col0 = blockIdx.y * 64;

    int arow = tid >> 2;           // 0..63
    int ak   = (tid & 3) * 4;      // 0,4,8,12
    int bk   = tid >> 4;           // 0..15
    int bcol = (tid & 15) * 4;     // 0..60
    bool bvec = (col0 + 64 <= Nc);

    float acc[4][4];
#pragma unroll
    for (int i = 0; i < 4; i++)
#pragma unroll
        for (int j = 0; j < 4; j++) acc[i][j] = 0.0f;

    for (int kb = 0; kb < K; kb += 16) {
        float4 av = make_float4(0.f,0.f,0.f,0.f);
        if (row0 + arow < M)
            av = *(const float4*)(A + (size_t)(row0 + arow)*K + kb + ak);
        As[(ak+0)*68 + arow] = av.x;
        As[(ak+1)*68 + arow] = av.y;
        As[(ak+2)*68 + arow] = av.z;
        As[(ak+3)*68 + arow] = av.w;
        if (bvec) {
            float4 bv = *(const float4*)(B + (size_t)(kb + bk)*Nc + col0 + bcol);
            *(float4*)&Bs[bk*68 + bcol] = bv;
        } else {
#pragma unroll
            for (int j = 0; j < 4; j++) {
                int c = col0 + bcol + j;
                Bs[bk*68 + bcol + j] = (c < Nc) ? B[(size_t)(kb + bk)*Nc + c] : 0.0f;
            }
        }
        __syncthreads();
#pragma unroll
        for (int kk = 0; kk < 16; kk++) {
            float4 a = *(const float4*)&As[kk*68 + ty*4];
            float4 b = *(const float4*)&Bs[kk*68 + tx*4];
            acc[0][0] += a.x*b.x; acc[0][1] += a.x*b.y; acc[0][2] += a.x*b.z; acc[0][3] += a.x*b.w;
            acc[1][0] += a.y*b.x; acc[1][1] += a.y*b.y; acc[1][2] += a.y*b.z; acc[1][3] += a.y*b.w;
            acc[2][0] += a.z*b.x; acc[2][1] += a.z*b.y; acc[2][2] += a.z*b.z; acc[2][3] += a.z*b.w;
            acc[3][0] += a.w*b.x; acc[3][1] += a.w*b.y; acc[3][2] += a.w*b.z; acc[3][3] += a.w*b.w;
        }
        __syncthreads();
    }

#pragma unroll
    for (int i = 0; i < 4; i++) {
        int r = row0 + ty*4 + i;
        if (r >= M) continue;
#pragma unroll
        for (int j = 0; j < 4; j++) {
            int c = col0 + tx*4 + j;
            if (c >= Nc) continue;
            float v = acc[i][j];
            if (bias) v += bias[c];
            float* cp = C + (size_t)r*Nc + c;
            if (mode == 1)      v = 0.5f * v * (1.0f + erff(v * 0.70710678118654752f));
            else if (mode == 2) v = fmaxf(v, 0.0f);
            else if (mode == 3) v += *cp;
            *cp = v;
        }
    }
}

// ---------------- fused QKV GEMM: z dim picks {q,k,v}; A = d_hn, K=Nc=128 ----------------
__global__ void qkv_gemm_kernel(const float* __restrict__ Wq, const float* __restrict__ Wk,
                                const float* __restrict__ Wv) {
    __shared__ float As[16*68];
    __shared__ float Bs[16*68];
    const float* A = d_hn;
    const float* B = (blockIdx.z == 0) ? Wq : (blockIdx.z == 1) ? Wk : Wv;
    float* C = (blockIdx.z == 0) ? d_q : (blockIdx.z == 1) ? d_k : d_v;

    int tid = threadIdx.x;
    int tx = tid & 15, ty = tid >> 4;
    int row0 = blockIdx.x * 64;
    int col0 = blockIdx.y * 64;

    int arow = tid >> 2;
    int ak   = (tid & 3) * 4;
    int bk   = tid >> 4;
    int bcol = (tid & 15) * 4;

    float acc[4][4];
#pragma unroll
    for (int i = 0; i < 4; i++)
#pragma unroll
        for (int j = 0; j < 4; j++) acc[i][j] = 0.0f;

#pragma unroll
    for (int kb = 0; kb < H_DIM; kb += 16) {
        float4 av = *(const float4*)(A + (size_t)(row0 + arow)*H_DIM + kb + ak);
        As[(ak+0)*68 + arow] = av.x;
        As[(ak+1)*68 + arow] = av.y;
        As[(ak+2)*68 + arow] = av.z;
        As[(ak+3)*68 + arow] = av.w;
        *(float4*)&Bs[bk*68 + bcol] = *(const float4*)(B + (size_t)(kb + bk)*H_DIM + col0 + bcol);
        __syncthreads();
#pragma unroll
        for (int kk = 0; kk < 16; kk++) {
            float4 a = *(const float4*)&As[kk*68 + ty*4];
            float4 b = *(const float4*)&Bs[kk*68 + tx*4];
            acc[0][0] += a.x*b.x; acc[0][1] += a.x*b.y; acc[0][2] += a.x*b.z; acc[0][3] += a.x*b.w;
            acc[1][0] += a.y*b.x; acc[1][1] += a.y*b.y; acc[1][2] += a.y*b.z; acc[1][3] += a.y*b.w;
            acc[2][0] += a.z*b.x; acc[2][1] += a.z*b.y; acc[2][2] += a.z*b.z; acc[2][3] += a.z*b.w;
            acc[3][0] += a.w*b.x; acc[3][1] += a.w*b.y; acc[3][2] += a.w*b.z; acc[3][3] += a.w*b.w;
        }
        __syncthreads();
    }

#pragma unroll
    for (int i = 0; i < 4; i++) {
        int r = row0 + ty*4 + i;
        float4 o = make_float4(acc[i][0], acc[i][1], acc[i][2], acc[i][3]);
        *(float4*)(C + (size_t)r*H_DIM + col0 + tx*4) = o;
    }
}

// ---------------- attention: one warp per dst node, online softmax; h += agg ----------------
__global__ void attn_kernel(const float* __restrict__ fp_l, const float* __restrict__ fd_l) {
    __shared__ float sfp[11];
    __shared__ float sfd[25];
    int tid = threadIdx.x;
    if (tid < 11) sfp[tid] = fp_l[tid];
    if (tid >= 32 && tid < 57) sfd[tid - 32] = fd_l[tid - 32];
    __syncthreads();

    int warp = blockIdx.x * (blockDim.x >> 5) + (tid >> 5);
    int lane = tid & 31;
    if (warp >= N_NODES) return;

    int beg = d_offs[warp];
    int end = d_offs[warp + 1];
    float4 q4 = ((const float4*)(d_q + warp*H_DIM))[lane];
    const float scale = 0.0883883476483184406f;   // 128^-0.5

    float m = -1e30f, dsum = 0.0f;
    float4 acc = make_float4(0.f,0.f,0.f,0.f);

    int e = beg;
    for (; e + 2 <= end; e += 2) {
        int w0 = d_packed[e];
        int w1 = d_packed[e + 1];
        int s0 = w0 & 8191;
        int s1 = w1 & 8191;
        float4 k0 = ((const float4*)(d_k + s0*H_DIM))[lane];
        float4 k1 = ((const float4*)(d_k + s1*H_DIM))[lane];
        float p0 = q4.x*k0.x + q4.y*k0.y + q4.z*k0.z + q4.w*k0.w;
        float p1 = q4.x*k1.x + q4.y*k1.y + q4.z*k1.z + q4.w*k1.w;
#pragma unroll
        for (int o = 16; o; o >>= 1) {
            p0 += __shfl_xor_sync(0xffffffffu, p0, o);
            p1 += __shfl_xor_sync(0xffffffffu, p1, o);
        }
        float sc0 = p0*scale + sfp[(w0 >> 13) & 15] + sfd[(w0 >> 17) & 31];
        float sc1 = p1*scale + sfp[(w1 >> 13) & 15] + sfd[(w1 >> 17) & 31];
        float4 v0 = ((const float4*)(d_v + s0*H_DIM))[lane];
        float4 v1 = ((const float4*)(d_v + s1*H_DIM))[lane];
        float nm = fmaxf(m, fmaxf(sc0, sc1));
        float f  = __expf(m - nm);
        float e0 = __expf(sc0 - nm);
        float e1 = __expf(sc1 - nm);
        dsum  = dsum*f + e0 + e1;
        acc.x = acc.x*f + e0*v0.x + e1*v1.x;
        acc.y = acc.y*f + e0*v0.y + e1*v1.y;
        acc.z = acc.z*f + e0*v0.z + e1*v1.z;
        acc.w = acc.w*f + e0*v0.w + e1*v1.w;
        m = nm;
    }
    if (e < end) {
        int w = d_packed[e];
        int s = w & 8191;
        float4 k4 = ((const float4*)(d_k + s*H_DIM))[lane];
        float p = q4.x*k4.x + q4.y*k4.y + q4.z*k4.z + q4.w*k4.w;
#pragma unroll
        for (int o = 16; o; o >>= 1) p += __shfl_xor_sync(0xffffffffu, p, o);
        float score = p*scale + sfp[(w >> 13) & 15] + sfd[(w >> 17) & 31];
        float4 v4 = ((const float4*)(d_v + s*H_DIM))[lane];
        float nm = fmaxf(m, score);
        float f  = __expf(m - nm);
        float we = __expf(score - nm);
        dsum  = dsum*f + we;
        acc.x = acc.x*f + we*v4.x;
        acc.y = acc.y*f + we*v4.y;
        acc.z = acc.z*f + we*v4.z;
        acc.w = acc.w*f + we*v4.w;
        m = nm;
    }
    if (end > beg) {
        float inv = 1.0f / dsum;   // denom >= 1, +1e-16 negligible
        float4* hp = (float4*)(d_h + warp*H_DIM) + lane;
        float4 hv = *hp;
        hv.x += acc.x*inv; hv.y += acc.y*inv; hv.z += acc.z*inv; hv.w += acc.w*inv;
        *hp = hv;
    }
}

// ---------------- mean pool (sums) ----------------
__global__ void pool_kernel(const int* __restrict__ batch) {
    int d  = threadIdx.x;            // 128 threads, one per dim
    int n0 = blockIdx.x * 64;        // grid 128 -> 64 nodes/block
    int curg = batch[n0];
    float run = 0.0f;
    for (int n = n0; n < n0 + 64; n++) {
        int g = batch[n];
        if (g != curg) {
            atomicAdd(&d_pooled[curg*H_DIM + d], run);
            run = 0.0f; curg = g;
        }
        run += d_h[n*H_DIM + d];
    }
    atomicAdd(&d_pooled[curg*H_DIM + d], run);
}

// ---------------- classifier head (single block) ----------------
__global__ void cls_kernel(const int* __restrict__ batch,
                           const float* __restrict__ W1, const float* __restrict__ b1,
                           const float* __restrict__ W2, const float* __restrict__ b2,
                           float* __restrict__ out) {
    __shared__ float g[NGRAPH*H_DIM];
    __shared__ float hid[NGRAPH*64];
    __shared__ int cnt[NGRAPH];
    int tid = threadIdx.x;
    if (tid < NGRAPH) cnt[tid] = 0;
    __syncthreads();
    for (int i = tid; i < N_NODES; i += 256) atomicAdd(&cnt[batch[i]], 1);
    __syncthreads();
    for (int idx = tid; idx < NGRAPH*H_DIM; idx += 256) {
        int gi = idx / H_DIM;
        float c = (float)max(cnt[gi], 1);
        g[idx] = d_pooled[idx] / c;
    }
    __syncthreads();
    for (int idx = tid; idx < NGRAPH*64; idx += 256) {
        int i = idx >> 6, j = idx & 63;
        float sum = b1[j];
        for (int kk = 0; kk < H_DIM; kk++) sum += g[i*H_DIM + kk] * W1[kk*64 + j];
        hid[idx] = fmaxf(sum, 0.0f);
    }
    __syncthreads();
    for (int idx = tid; idx < NGRAPH*OUT_DIM; idx += 256) {
        int i = idx / OUT_DIM, j = idx % OUT_DIM;
        float sum = b2[j];
        for (int kk = 0; kk < 64; kk++) sum += hid[i*64 + kk] * W2[kk*OUT_DIM + j];
        out[idx] = sum;
    }
}

// ---------------- host launcher ----------------
extern "C" void kernel_launch(void* const* d_in, const int* in_sizes, int n_in,
                              void* d_out, int out_size) {
    const float* x      = (const float*)d_in[0];
    const int*   ei     = (const int*)  d_in[1];
    const int*   pmat   = (const int*)  d_in[2];
    const int*   dmat   = (const int*)  d_in[3];
    const int*   batch  = (const int*)  d_in[4];
    const float* in_W   = (const float*)d_in[5];
    const float* in_b   = (const float*)d_in[6];
    const float* ln1_s  = (const float*)d_in[7];
    const float* ln1_b  = (const float*)d_in[8];
    const float* Wq     = (const float*)d_in[9];
    const float* Wk     = (const float*)d_in[10];
    const float* Wv     = (const float*)d_in[11];
    const float* fp     = (const float*)d_in[12];
    const float* fd     = (const float*)d_in[13];
    const float* ln2_s  = (const float*)d_in[14];
    const float* ln2_b  = (const float*)d_in[15];
    const float* W1     = (const float*)d_in[16];
    const float* b1     = (const float*)d_in[17];
    const float* W2     = (const float*)d_in[18];
    const float* b2     = (const float*)d_in[19];
    const float* cW1    = (const float*)d_in[20];
    const float* cb1    = (const float*)d_in[21];
    const float* cW2    = (const float*)d_in[22];
    const float* cb2    = (const float*)d_in[23];
    float* out = (float*)d_out;

    static float *h = nullptr, *hn, *t1;
    if (!h) {
        cudaGetSymbolAddress((void**)&h,  d_h);
        cudaGetSymbolAddress((void**)&hn, d_hn);
        cudaGetSymbolAddress((void**)&t1, d_t1);
    }

    // preprocess: sort edges by dst (counting sort), gather structural biases
    zero_pre_kernel<<<32, 256>>>();
    hist_kernel<<<N_EDGES/256, 256>>>(ei + N_EDGES);
    scan_kernel<<<1, 1024>>>();
    scatter_kernel<<<N_EDGES/256, 256>>>(ei, ei + N_EDGES, pmat, dmat);

    // input projection: h = x @ in_W + in_b
    sgemm_kernel<<<dim3(N_NODES/64, 2), 256>>>(x, in_W, in_b, h, N_NODES, IN_DIM, H_DIM, 0);

    for (int l = 0; l < L_LAYERS; l++) {
        ln_kernel<<<N_NODES/8, 256>>>(ln1_s + l*H_DIM, ln1_b + l*H_DIM);
        qkv_gemm_kernel<<<dim3(N_NODES/64, 2, 3), 256>>>(Wq + l*H_DIM*H_DIM, Wk + l*H_DIM*H_DIM, Wv + l*H_DIM*H_DIM);
        attn_kernel<<<N_NODES/8, 256>>>(fp + l*11, fd + l*25);
        ln_kernel<<<N_NODES/8, 256>>>(ln2_s + l*H_DIM, ln2_b + l*H_DIM);
        sgemm_kernel<<<dim3(N_NODES/64, 4), 256>>>(hn, W1 + l*H_DIM*2*H_DIM, b1 + l*2*H_DIM, t1, N_NODES, H_DIM, 2*H_DIM, 1);
        sgemm_kernel<<<dim3(N_NODES/64, 2), 256>>>(t1, W2 + l*2*H_DIM*H_DIM, b2 + l*H_DIM, h, N_NODES, 2*H_DIM, H_DIM, 3);
    }

    pool_kernel<<<N_NODES/64, H_DIM>>>(batch);
    cls_kernel<<<1, 256>>>(batch, cW1, cb1, cW2, cb2, out);
}

// round 4
// speedup vs baseline: 1.0524x; 1.0524x over previous
#include <cuda_runtime.h>
#include <math.h>
#include <stdint.h>

#define N_NODES 8192
#define N_EDGES 262144
#define IN_DIM  64
#define H_DIM   128
#define L_LAYERS 4
#define NGRAPH  32
#define OUT_DIM 10

// ---------------- scratch (static device globals; no allocation) ----------------
__device__ float d_h [N_NODES*H_DIM];
__device__ float d_hn[N_NODES*H_DIM];
__device__ float d_q [N_NODES*H_DIM];
__device__ float d_k [N_NODES*H_DIM];
__device__ float d_v [N_NODES*H_DIM];
__device__ float d_t1[N_NODES*2*H_DIM];
__device__ int   d_counts[N_NODES];
__device__ int   d_offs[N_NODES+1];
__device__ int   d_cursor[N_NODES];
__device__ int   d_packed[N_EDGES];      // src | (p<<13) | (d<<17)
__device__ float d_pooled[NGRAPH*H_DIM];

// ---------------- preprocess ----------------
__global__ void zero_pre_kernel() {
    int i = blockIdx.x*blockDim.x + threadIdx.x;
    if (i < N_NODES) d_counts[i] = 0;
    if (i < NGRAPH*H_DIM) d_pooled[i] = 0.0f;
}

__global__ void hist_kernel(const int* __restrict__ dst) {
    int e = blockIdx.x*blockDim.x + threadIdx.x;
    if (e < N_EDGES) atomicAdd(&d_counts[dst[e]], 1);
}

// single-block exclusive scan over 8192 counts (1024 threads x 8)
__global__ void scan_kernel() {
    __shared__ int s[1024];
    int tid = threadIdx.x;
    int local[8]; int sum = 0;
#pragma unroll
    for (int j = 0; j < 8; j++) { local[j] = sum; sum += d_counts[tid*8 + j]; }
    s[tid] = sum;
    __syncthreads();
    for (int off = 1; off < 1024; off <<= 1) {
        int v = 0;
        if (tid >= off) v = s[tid - off];
        __syncthreads();
        s[tid] += v;
        __syncthreads();
    }
    int base = tid ? s[tid-1] : 0;
#pragma unroll
    for (int j = 0; j < 8; j++) {
        int val = base + local[j];
        d_offs[tid*8 + j]   = val;
        d_cursor[tid*8 + j] = val;
    }
    if (tid == 1023) d_offs[N_NODES] = s[1023];
}

__global__ void scatter_kernel(const int* __restrict__ src, const int* __restrict__ dst,
                               const int* __restrict__ pmat, const int* __restrict__ dmat) {
    int e = blockIdx.x*blockDim.x + threadIdx.x;
    if (e >= N_EDGES) return;
    int s = src[e], d = dst[e];
    int pos = atomicAdd(&d_cursor[d], 1);
    long idx = (long)s * N_NODES + d;
    int p  = pmat[idx];
    int dd = dmat[idx];
    d_packed[pos] = s | (p << 13) | (dd << 17);
}

// ---------------- layernorm: d_hn = LN(d_h) * s + b ----------------
__global__ void ln_kernel(const float* __restrict__ sc, const float* __restrict__ bi) {
    int row  = blockIdx.x * 8 + (threadIdx.x >> 5);
    int lane = threadIdx.x & 31;
    float4 x = ((const float4*)(d_h + row*H_DIM))[lane];
    float sum = x.x + x.y + x.z + x.w;
#pragma unroll
    for (int o = 16; o; o >>= 1) sum += __shfl_xor_sync(0xffffffffu, sum, o);
    float mean = sum * (1.0f/128.0f);
    float dx0 = x.x - mean, dx1 = x.y - mean, dx2 = x.z - mean, dx3 = x.w - mean;
    float sq = dx0*dx0 + dx1*dx1 + dx2*dx2 + dx3*dx3;
#pragma unroll
    for (int o = 16; o; o >>= 1) sq += __shfl_xor_sync(0xffffffffu, sq, o);
    float inv = rsqrtf(sq * (1.0f/128.0f) + 1e-5f);
    float4 s4 = ((const float4*)sc)[lane];
    float4 b4 = ((const float4*)bi)[lane];
    float4 o;
    o.x = dx0*inv*s4.x + b4.x;
    o.y = dx1*inv*s4.y + b4.y;
    o.z = dx2*inv*s4.z + b4.z;
    o.w = dx3*inv*s4.w + b4.w;
    ((float4*)(d_hn + row*H_DIM))[lane] = o;
}

// ---------------- tf32x3 tensor-core GEMM ----------------
// C = act(A[M,K] @ B[K,Nc] + bias); 3xTF32 split for ~fp32 accuracy.
// Block tile 128(M) x 64(N), BK=16, 256 threads (8 warps, 4m x 2n).
// blockIdx.z selects among up to 3 (B,C) pairs (fused QKV).
// mode: 0=store, 1=gelu(exact erf), 2=relu, 3=add to C (residual)

__device__ __forceinline__ void split_tf32(float x, float& hi, float& lo) {
    uint32_t uh, ul;
    asm("cvt.rna.tf32.f32 %0, %1;" : "=r"(uh) : "f"(x));
    hi = __uint_as_float(uh);
    float r = x - hi;
    asm("cvt.rna.tf32.f32 %0, %1;" : "=r"(ul) : "f"(r));
    lo = __uint_as_float(ul);
}

__device__ __forceinline__ void mma_tf32(float* d, const uint32_t* a, const uint32_t* b) {
    asm volatile("mma.sync.aligned.m16n8k8.row.col.f32.tf32.tf32.f32 "
        "{%0,%1,%2,%3}, {%4,%5,%6,%7}, {%8,%9}, {%0,%1,%2,%3};"
        : "+f"(d[0]), "+f"(d[1]), "+f"(d[2]), "+f"(d[3])
        : "r"(a[0]), "r"(a[1]), "r"(a[2]), "r"(a[3]), "r"(b[0]), "r"(b[1]));
}

#define AST 20   // A smem stride (16 + 4): frag addr 4*row+col -> conflict-free
#define BST 72   // B smem stride (64 + 8): frag addr 8*k+n   -> conflict-free

__global__ __launch_bounds__(256) void tf32_gemm_kernel(
        const float* __restrict__ A,
        const float* __restrict__ B0, const float* __restrict__ B1, const float* __restrict__ B2,
        const float* __restrict__ bias,
        float* __restrict__ C0, float* __restrict__ C1, float* __restrict__ C2,
        int M, int K, int Nc, int mode) {
    __shared__ float Ahi[128][AST], Alo[128][AST];
    __shared__ float Bhi[16][BST],  Blo[16][BST];

    const float* B = (blockIdx.z == 0) ? B0 : (blockIdx.z == 1) ? B1 : B2;
    float*       C = (blockIdx.z == 0) ? C0 : (blockIdx.z == 1) ? C1 : C2;

    int tid = threadIdx.x;
    int wid = tid >> 5;
    int lane = tid & 31;
    int g   = lane >> 2;     // groupID 0..7
    int tig = lane & 3;      // thread-in-group 0..3
    int wm = wid & 3;        // warp m 0..3  -> 32 rows each
    int wn = wid >> 2;       // warp n 0..1  -> 32 cols each
    int row0 = blockIdx.x * 128;
    int col0 = blockIdx.y * 64;

    // global load indices
    int arow = tid >> 1;              // 0..127
    int acg  = (tid & 1) * 8;         // 0 or 8
    int bk_  = tid >> 4;              // 0..15
    int bn   = (tid & 15) * 4;        // 0..60

    float acc[2][4][4];
#pragma unroll
    for (int mi = 0; mi < 2; mi++)
#pragma unroll
        for (int ni = 0; ni < 4; ni++)
#pragma unroll
            for (int r = 0; r < 4; r++) acc[mi][ni][r] = 0.0f;

    for (int kb = 0; kb < K; kb += 16) {
        // load + split A tile [128 x 16]
        const float* ap = A + (size_t)(row0 + arow)*K + kb + acg;
        float4 av0 = *(const float4*)ap;
        float4 av1 = *(const float4*)(ap + 4);
        float h0,l0,h1,l1,h2,l2,h3,l3;
        split_tf32(av0.x,h0,l0); split_tf32(av0.y,h1,l1); split_tf32(av0.z,h2,l2); split_tf32(av0.w,h3,l3);
        *(float4*)&Ahi[arow][acg]   = make_float4(h0,h1,h2,h3);
        *(float4*)&Alo[arow][acg]   = make_float4(l0,l1,l2,l3);
        split_tf32(av1.x,h0,l0); split_tf32(av1.y,h1,l1); split_tf32(av1.z,h2,l2); split_tf32(av1.w,h3,l3);
        *(float4*)&Ahi[arow][acg+4] = make_float4(h0,h1,h2,h3);
        *(float4*)&Alo[arow][acg+4] = make_float4(l0,l1,l2,l3);
        // load + split B tile [16 x 64]
        float4 bv = *(const float4*)(B + (size_t)(kb + bk_)*Nc + col0 + bn);
        split_tf32(bv.x,h0,l0); split_tf32(bv.y,h1,l1); split_tf32(bv.z,h2,l2); split_tf32(bv.w,h3,l3);
        *(float4*)&Bhi[bk_][bn] = make_float4(h0,h1,h2,h3);
        *(float4*)&Blo[bk_][bn] = make_float4(l0,l1,l2,l3);
        __syncthreads();

#pragma unroll
        for (int kk = 0; kk < 16; kk += 8) {
            uint32_t ah[2][4], al[2][4], bh[4][2], bl[4][2];
#pragma unroll
            for (int mi = 0; mi < 2; mi++) {
                int rb = wm*32 + mi*16 + g;
                ah[mi][0] = __float_as_uint(Ahi[rb    ][kk+tig]);
                ah[mi][1] = __float_as_uint(Ahi[rb + 8][kk+tig]);
                ah[mi][2] = __float_as_uint(Ahi[rb    ][kk+tig+4]);
                ah[mi][3] = __float_as_uint(Ahi[rb + 8][kk+tig+4]);
                al[mi][0] = __float_as_uint(Alo[rb    ][kk+tig]);
                al[mi][1] = __float_as_uint(Alo[rb + 8][kk+tig]);
                al[mi][2] = __float_as_uint(Alo[rb    ][kk+tig+4]);
                al[mi][3] = __float_as_uint(Alo[rb + 8][kk+tig+4]);
            }
#pragma unroll
            for (int ni = 0; ni < 4; ni++) {
                int nb = wn*32 + ni*8 + g;
                bh[ni][0] = __float_as_uint(Bhi[kk+tig  ][nb]);
                bh[ni][1] = __float_as_uint(Bhi[kk+tig+4][nb]);
                bl[ni][0] = __float_as_uint(Blo[kk+tig  ][nb]);
                bl[ni][1] = __float_as_uint(Blo[kk+tig+4][nb]);
            }
#pragma unroll
            for (int mi = 0; mi < 2; mi++)
#pragma unroll
                for (int ni = 0; ni < 4; ni++) {
                    mma_tf32(acc[mi][ni], al[mi], bh[ni]);
                    mma_tf32(acc[mi][ni], ah[mi], bl[ni]);
                    mma_tf32(acc[mi][ni], ah[mi], bh[ni]);
                }
        }
        __syncthreads();
    }

    // epilogue
#pragma unroll
    for (int mi = 0; mi < 2; mi++) {
        int r0 = row0 + wm*32 + mi*16 + g;
#pragma unroll
        for (int ni = 0; ni < 4; ni++) {
            int c = col0 + wn*32 + ni*8 + tig*2;
            float vals[4] = {acc[mi][ni][0], acc[mi][ni][1], acc[mi][ni][2], acc[mi][ni][3]};
            if (bias) {
                float bb0 = bias[c], bb1 = bias[c+1];
                vals[0] += bb0; vals[1] += bb1; vals[2] += bb0; vals[3] += bb1;
            }
#pragma unroll
            for (int r = 0; r < 4; r++) {
                int rr = (r < 2) ? r0 : r0 + 8;
                int cc = c + (r & 1);
                float* cp = C + (size_t)rr*Nc + cc;
                float vv = vals[r];
                if (mode == 1)      vv = 0.5f * vv * (1.0f + erff(vv * 0.70710678118654752f));
                else if (mode == 2) vv = fmaxf(vv, 0.0f);
                else if (mode == 3) vv += *cp;
                *cp = vv;
            }
        }
    }
}

// ---------------- attention: one warp per dst node, online softmax; h += agg ----------------
__global__ void attn_kernel(const float* __restrict__ fp_l, const float* __restrict__ fd_l) {
    __shared__ float sfp[11];
    __shared__ float sfd[25];
    int tid = threadIdx.x;
    if (tid < 11) sfp[tid] = fp_l[tid];
    if (tid >= 32 && tid < 57) sfd[tid - 32] = fd_l[tid - 32];
    __syncthreads();

    int warp = blockIdx.x * (blockDim.x >> 5) + (tid >> 5);
    int lane = tid & 31;
    if (warp >= N_NODES) return;

    int beg = d_offs[warp];
    int end = d_offs[warp + 1];
    float4 q4 = ((const float4*)(d_q + warp*H_DIM))[lane];
    const float scale = 0.0883883476483184406f;   // 128^-0.5

    float m = -1e30f, dsum = 0.0f;
    float4 acc = make_float4(0.f,0.f,0.f,0.f);

    int e = beg;
    for (; e + 2 <= end; e += 2) {
        int w0 = d_packed[e];
        int w1 = d_packed[e + 1];
        int s0 = w0 & 8191;
        int s1 = w1 & 8191;
        float4 k0 = ((const float4*)(d_k + s0*H_DIM))[lane];
        float4 k1 = ((const float4*)(d_k + s1*H_DIM))[lane];
        float p0 = q4.x*k0.x + q4.y*k0.y + q4.z*k0.z + q4.w*k0.w;
        float p1 = q4.x*k1.x + q4.y*k1.y + q4.z*k1.z + q4.w*k1.w;
#pragma unroll
        for (int o = 16; o; o >>= 1) {
            p0 += __shfl_xor_sync(0xffffffffu, p0, o);
            p1 += __shfl_xor_sync(0xffffffffu, p1, o);
        }
        float sc0 = p0*scale + sfp[(w0 >> 13) & 15] + sfd[(w0 >> 17) & 31];
        float sc1 = p1*scale + sfp[(w1 >> 13) & 15] + sfd[(w1 >> 17) & 31];
        float4 v0 = ((const float4*)(d_v + s0*H_DIM))[lane];
        float4 v1 = ((const float4*)(d_v + s1*H_DIM))[lane];
        float nm = fmaxf(m, fmaxf(sc0, sc1));
        float f  = __expf(m - nm);
        float e0 = __expf(sc0 - nm);
        float e1 = __expf(sc1 - nm);
        dsum  = dsum*f + e0 + e1;
        acc.x = acc.x*f + e0*v0.x + e1*v1.x;
        acc.y = acc.y*f + e0*v0.y + e1*v1.y;
        acc.z = acc.z*f + e0*v0.z + e1*v1.z;
        acc.w = acc.w*f + e0*v0.w + e1*v1.w;
        m = nm;
    }
    if (e < end) {
        int w = d_packed[e];
        int s = w & 8191;
        float4 k4 = ((const float4*)(d_k + s*H_DIM))[lane];
        float p = q4.x*k4.x + q4.y*k4.y + q4.z*k4.z + q4.w*k4.w;
#pragma unroll
        for (int o = 16; o; o >>= 1) p += __shfl_xor_sync(0xffffffffu, p, o);
        float score = p*scale + sfp[(w >> 13) & 15] + sfd[(w >> 17) & 31];
        float4 v4 = ((const float4*)(d_v + s*H_DIM))[lane];
        float nm = fmaxf(m, score);
        float f  = __expf(m - nm);
        float we = __expf(score - nm);
        dsum  = dsum*f + we;
        acc.x = acc.x*f + we*v4.x;
        acc.y = acc.y*f + we*v4.y;
        acc.z = acc.z*f + we*v4.z;
        acc.w = acc.w*f + we*v4.w;
        m = nm;
    }
    if (end > beg) {
        float inv = 1.0f / dsum;
        float4* hp = (float4*)(d_h + warp*H_DIM) + lane;
        float4 hv = *hp;
        hv.x += acc.x*inv; hv.y += acc.y*inv; hv.z += acc.z*inv; hv.w += acc.w*inv;
        *hp = hv;
    }
}

// ---------------- mean pool (sums) ----------------
__global__ void pool_kernel(const int* __restrict__ batch) {
    int d  = threadIdx.x;
    int n0 = blockIdx.x * 64;
    int curg = batch[n0];
    float run = 0.0f;
    for (int n = n0; n < n0 + 64; n++) {
        int g = batch[n];
        if (g != curg) {
            atomicAdd(&d_pooled[curg*H_DIM + d], run);
            run = 0.0f; curg = g;
        }
        run += d_h[n*H_DIM + d];
    }
    atomicAdd(&d_pooled[curg*H_DIM + d], run);
}

// ---------------- classifier head (single block) ----------------
__global__ void cls_kernel(const int* __restrict__ batch,
                           const float* __restrict__ W1, const float* __restrict__ b1,
                           const float* __restrict__ W2, const float* __restrict__ b2,
                           float* __restrict__ out) {
    __shared__ float g[NGRAPH*H_DIM];
    __shared__ float hid[NGRAPH*64];
    __shared__ int cnt[NGRAPH];
    int tid = threadIdx.x;
    if (tid < NGRAPH) cnt[tid] = 0;
    __syncthreads();
    for (int i = tid; i < N_NODES; i += 256) atomicAdd(&cnt[batch[i]], 1);
    __syncthreads();
    for (int idx = tid; idx < NGRAPH*H_DIM; idx += 256) {
        int gi = idx / H_DIM;
        float c = (float)max(cnt[gi], 1);
        g[idx] = d_pooled[idx] / c;
    }
    __syncthreads();
    for (int idx = tid; idx < NGRAPH*64; idx += 256) {
        int i = idx >> 6, j = idx & 63;
        float sum = b1[j];
        for (int kk = 0; kk < H_DIM; kk++) sum += g[i*H_DIM + kk] * W1[kk*64 + j];
        hid[idx] = fmaxf(sum, 0.0f);
    }
    __syncthreads();
    for (int idx = tid; idx < NGRAPH*OUT_DIM; idx += 256) {
        int i = idx / OUT_DIM, j = idx % OUT_DIM;
        float sum = b2[j];
        for (int kk = 0; kk < 64; kk++) sum += hid[i*64 + kk] * W2[kk*OUT_DIM + j];
        out[idx] = sum;
    }
}

// ---------------- host launcher ----------------
extern "C" void kernel_launch(void* const* d_in, const int* in_sizes, int n_in,
                              void* d_out, int out_size) {
    const float* x      = (const float*)d_in[0];
    const int*   ei     = (const int*)  d_in[1];
    const int*   pmat   = (const int*)  d_in[2];
    const int*   dmat   = (const int*)  d_in[3];
    const int*   batch  = (const int*)  d_in[4];
    const float* in_W   = (const float*)d_in[5];
    const float* in_b   = (const float*)d_in[6];
    const float* ln1_s  = (const float*)d_in[7];
    const float* ln1_b  = (const float*)d_in[8];
    const float* Wq     = (const float*)d_in[9];
    const float* Wk     = (const float*)d_in[10];
    const float* Wv     = (const float*)d_in[11];
    const float* fp     = (const float*)d_in[12];
    const float* fd     = (const float*)d_in[13];
    const float* ln2_s  = (const float*)d_in[14];
    const float* ln2_b  = (const float*)d_in[15];
    const float* W1     = (const float*)d_in[16];
    const float* b1     = (const float*)d_in[17];
    const float* W2     = (const float*)d_in[18];
    const float* b2     = (const float*)d_in[19];
    const float* cW1    = (const float*)d_in[20];
    const float* cb1    = (const float*)d_in[21];
    const float* cW2    = (const float*)d_in[22];
    const float* cb2    = (const float*)d_in[23];
    float* out = (float*)d_out;

    static float *h = nullptr, *hn, *q, *k, *v, *t1;
    if (!h) {
        cudaGetSymbolAddress((void**)&h,  d_h);
        cudaGetSymbolAddress((void**)&hn, d_hn);
        cudaGetSymbolAddress((void**)&q,  d_q);
        cudaGetSymbolAddress((void**)&k,  d_k);
        cudaGetSymbolAddress((void**)&v,  d_v);
        cudaGetSymbolAddress((void**)&t1, d_t1);
    }

    // preprocess: sort edges by dst (counting sort), gather structural biases
    zero_pre_kernel<<<32, 256>>>();
    hist_kernel<<<N_EDGES/256, 256>>>(ei + N_EDGES);
    scan_kernel<<<1, 1024>>>();
    scatter_kernel<<<N_EDGES/256, 256>>>(ei, ei + N_EDGES, pmat, dmat);

    // input projection: h = x @ in_W + in_b
    tf32_gemm_kernel<<<dim3(N_NODES/128, 2, 1), 256>>>(
        x, in_W, nullptr, nullptr, in_b, h, nullptr, nullptr,
        N_NODES, IN_DIM, H_DIM, 0);

    for (int l = 0; l < L_LAYERS; l++) {
        ln_kernel<<<N_NODES/8, 256>>>(ln1_s + l*H_DIM, ln1_b + l*H_DIM);
        tf32_gemm_kernel<<<dim3(N_NODES/128, 2, 3), 256>>>(
            hn, Wq + l*H_DIM*H_DIM, Wk + l*H_DIM*H_DIM, Wv + l*H_DIM*H_DIM,
            nullptr, q, k, v, N_NODES, H_DIM, H_DIM, 0);
        attn_kernel<<<N_NODES/8, 256>>>(fp + l*11, fd + l*25);
        ln_kernel<<<N_NODES/8, 256>>>(ln2_s + l*H_DIM, ln2_b + l*H_DIM);
        tf32_gemm_kernel<<<dim3(N_NODES/128, 4, 1), 256>>>(
            hn, W1 + l*H_DIM*2*H_DIM, nullptr, nullptr, b1 + l*2*H_DIM,
            t1, nullptr, nullptr, N_NODES, H_DIM, 2*H_DIM, 1);
        tf32_gemm_kernel<<<dim3(N_NODES/128, 2, 1), 256>>>(
            t1, W2 + l*2*H_DIM*H_DIM, nullptr, nullptr, b2 + l*H_DIM,
            h, nullptr, nullptr, N_NODES, 2*H_DIM, H_DIM, 3);
    }

    pool_kernel<<<N_NODES/64, H_DIM>>>(batch);
    cls_kernel<<<1, 256>>>(batch, cW1, cb1, cW2, cb2, out);
}